// round 8
// baseline (speedup 1.0000x reference)
#include <cuda_runtime.h>
#include <math.h>

#define B_   128
#define P_   2048
#define NB_  2000
#define NF_  250
#define NC_  16
#define R_   128
#define LS_  1750      // NB - NF
#define FT_  1751      // NB - NF + 1
#define NW_  63        // 32-bit words covering NB=2000
#define NWP_ 64        // padded row stride in words
#define LSP_ 1760      // padded LS stride: multiple of 32 so the last 32-wide
                       // transpose tile (t up to 1759) and k_sim's float4 reads
                       // stay inside the row (R7 bug: 1752 overflowed into the
                       // next sequence's row)
#define NSEQ_ (B_ * R_)

// ---------------- scratch (static device globals; no allocations) ----------------
__device__ float d_filt[FT_];
__device__ float d_stimdot[B_];
__device__ float d_gensig[B_ * LS_];
__device__ unsigned d_bm[B_ * NC_ * NWP_];      // bitmask of cc != 0
__device__ float d_uT[(size_t)NSEQ_ * LSP_];    // u transposed: [seq][t]

// ---------------- K1: filt_time ----------------
__global__ void k_filt(const float* __restrict__ stim_time,
                       const float* __restrict__ stf) {
    int warp = (blockIdx.x * blockDim.x + threadIdx.x) >> 5;
    int lane = threadIdx.x & 31;
    if (warp >= FT_) return;
    double a = 0.0;
    #pragma unroll
    for (int i = lane; i < NF_; i += 32)
        a += (double)stim_time[warp + i] * (double)stf[i];
    #pragma unroll
    for (int m = 16; m; m >>= 1) a += __shfl_xor_sync(0xffffffffu, a, m);
    if (lane == 0) d_filt[warp] = (float)a;
}

// ---------------- K2: stim_dot ----------------
__global__ void k_stimdot(const float* __restrict__ spat,
                          const float* __restrict__ sf) {
    int warp = (blockIdx.x * blockDim.x + threadIdx.x) >> 5;
    int lane = threadIdx.x & 31;
    if (warp >= B_) return;
    const float* row = spat + (size_t)warp * P_;
    double a = 0.0;
    for (int p = lane; p < P_; p += 32)
        a += (double)row[p] * (double)sf[p];
    #pragma unroll
    for (int m = 16; m; m >>= 1) a += __shfl_xor_sync(0xffffffffu, a, m);
    if (lane == 0) d_stimdot[warp] = (float)a;
}

// ---------------- K-pack: bitmask of cc != 0 ----------------
__global__ void k_pack(const float* __restrict__ cc) {
    int gid  = blockIdx.x * blockDim.x + threadIdx.x;
    int warp = gid >> 5;
    int lane = gid & 31;
    int row  = warp / NW_;
    int word = warp - row * NW_;
    if (row >= B_ * NC_) return;
    int elem = word * 32 + lane;
    float v = (elem < NB_) ? cc[(size_t)row * NB_ + elem] : 0.0f;
    unsigned m = __ballot_sync(0xffffffffu, v != 0.0f);
    if (lane == 0) d_bm[row * NWP_ + word] = m;
}

// ---------------- K-utr: transpose u[t][seq] -> uT[seq][t] (padded) ----------------
__global__ void __launch_bounds__(256)
k_utr(const float* __restrict__ u) {
    __shared__ float tile[32][33];
    const int tb = blockIdx.x;       // t-tile (0..54)
    const int sb = blockIdx.y;       // seq-tile (0..511)
    const int tx = threadIdx.x & 31;
    const int ty = threadIdx.x >> 5; // 0..7

    #pragma unroll
    for (int j = 0; j < 4; ++j) {
        int t = tb * 32 + ty + 8 * j;
        int s = sb * 32 + tx;
        tile[ty + 8 * j][tx] = (t < LS_) ? u[(size_t)t * NSEQ_ + s] : 0.0f;
    }
    __syncthreads();
    #pragma unroll
    for (int j = 0; j < 4; ++j) {
        int s = sb * 32 + ty + 8 * j;
        int t = tb * 32 + tx;        // <= 1759 < LSP_ = 1760: in-row
        d_uT[(size_t)s * LSP_ + t] = tile[tx][ty + 8 * j];
    }
}

// ---------------- K3: gensig (verified R5 version, untouched) ----------------
__global__ void __launch_bounds__(256)
k_gensig(const float* __restrict__ cK,
         const float* __restrict__ bias) {
    __shared__ double sKd[NC_ * 256];
    __shared__ unsigned sbm[NC_ * NWP_];

    const int tid = threadIdx.x;
    const int b   = blockIdx.y;

    for (int i = tid; i < NC_ * 256; i += 256) {
        int c = i >> 8, k = i & 255;
        sKd[i] = (k < NF_) ? (double)cK[c * NF_ + k] : 0.0;
    }
    for (int i = tid; i < NC_ * NWP_; i += 256)
        sbm[i] = d_bm[b * NC_ * NWP_ + i];
    __syncthreads();

    const int t = blockIdx.x * 256 + tid;
    if (t >= LS_) return;

    const int w0 = t >> 5;
    const int o  = t & 31;

    double a0 = 0.0, a1 = 0.0, a2 = 0.0, a3 = 0.0;
    #pragma unroll 1
    for (int c = 0; c < NC_; ++c) {
        const unsigned* bm = sbm + c * NWP_ + w0;
        const double*   kd = sKd + c * 256;
        #pragma unroll
        for (int k = 0; k < 8; k += 4) {
            unsigned w_0 = __funnelshift_r(bm[k],     bm[k + 1], o);
            unsigned w_1 = __funnelshift_r(bm[k + 1], bm[k + 2], o);
            unsigned w_2 = __funnelshift_r(bm[k + 2], bm[k + 3], o);
            unsigned w_3 = __funnelshift_r(bm[k + 3], bm[k + 4], o);
            while (w_0) { int i = __ffs(w_0) - 1; w_0 &= w_0 - 1; a0 += kd[((k    ) << 5) + i]; }
            while (w_1) { int i = __ffs(w_1) - 1; w_1 &= w_1 - 1; a1 += kd[((k + 1) << 5) + i]; }
            while (w_2) { int i = __ffs(w_2) - 1; w_2 &= w_2 - 1; a2 += kd[((k + 2) << 5) + i]; }
            while (w_3) { int i = __ffs(w_3) - 1; w_3 &= w_3 - 1; a3 += kd[((k + 3) << 5) + i]; }
        }
    }
    float coup = (float)((a0 + a1) + (a2 + a3));
    float sg = __fmul_rn(d_stimdot[b], d_filt[t]);
    sg = __fadd_rn(sg, bias[0]);
    d_gensig[b * LS_ + t] = __fadd_rn(sg, coup);
}

// ---------------- K4: simulation — R3 geometry (verified bit-exact) + coalesced u ----
// 4 sequences/warp, 8 lanes/seq, 32 taps/lane, rotation mod 32, 32-step blocks.
// u delivery: float4 from transposed uT (lane q holds t0+4q..t0+4q+3; ut for
// step s shfl'd from lane s>>2, element s&3 — same value as the verified path).
__global__ void __launch_bounds__(128, 6)
k_sim(const float* __restrict__ init,
      const float* __restrict__ ff,
      float* __restrict__ out) {
    const unsigned FULL = 0xffffffffu;
    const int lane = threadIdx.x & 31;
    const int gw   = (blockIdx.x * blockDim.x + threadIdx.x) >> 5;  // 0..4095
    const int b    = gw >> 5;         // 32 warps per b
    const int rq   = gw & 31;
    const int half = lane >> 3;       // 0..3: sequence within the warp
    const int q    = lane & 7;        // lane within the 8-lane group
    const int seq  = b * R_ + rq * 4 + half;

    float f[32], w[32];
    #pragma unroll
    for (int i = 0; i < 32; ++i) {
        int k = q * 32 + i;
        bool valid = (k < NF_);
        f[i] = valid ? ff[k] : 0.0f;
        w[i] = valid ? init[b * NF_ + k] : 0.0f;
    }

    float* orow = out + (size_t)seq * NB_;
    for (int k = q; k < NF_; k += 8)
        orow[k] = init[b * NF_ + k];

    const float* gens = d_gensig + b * LS_;
    const float* urow = d_uT + (size_t)seq * LSP_;
    const int src_half  = lane & 24;
    const int src_shift = src_half | ((q + 1) & 7);

    for (int t0 = 0; t0 < LS_; t0 += 32) {
        float gval = (t0 + lane < LS_) ? gens[t0 + lane] : 0.0f;
        // lane q holds u for t = t0+4q .. t0+4q+3 (128B contiguous per group)
        float4 uv = *(const float4*)(urow + t0 + 4 * q);
        float outv[4];
        outv[0] = outv[1] = outv[2] = outv[3] = 0.0f;

        #pragma unroll
        for (int s = 0; s < 32; ++s) {
            float a  = w[s & 31]        * f[0];
            float bb = w[(16 + s) & 31] * f[16];
            #pragma unroll
            for (int i = 1; i < 16; ++i) {
                a  = fmaf(w[(i + s) & 31],      f[i],      a);
                bb = fmaf(w[(16 + i + s) & 31], f[16 + i], bb);
            }
            float acc = a + bb;
            acc += __shfl_xor_sync(FULL, acc, 1);
            acc += __shfl_xor_sync(FULL, acc, 2);
            acc += __shfl_xor_sync(FULL, acc, 4);

            float gt = __shfl_sync(FULL, gval, s);
            float uu = (s & 3) == 0 ? uv.x : (s & 3) == 1 ? uv.y
                     : (s & 3) == 2 ? uv.z : uv.w;
            float ut = __shfl_sync(FULL, uu, src_half | (s >> 2));

            float g = gt + acc;
            float e = expf(-g);
            float sig = 1.0f / (1.0f + e);
            float spike = (ut < sig) ? 1.0f : 0.0f;

            if (q == (s & 7)) outv[s >> 3] = spike;

            float inc = __shfl_sync(FULL, w[s & 31], src_shift);
            w[s & 31] = inc;
            if (q == 7) w[(s + 26) & 31] = spike;
        }

        #pragma unroll
        for (int m = 0; m < 4; ++m) {
            int t = t0 + 8 * m + q;
            if (t < LS_) orow[NF_ + t] = outv[m];
        }
    }
}

// ---------------- launch ----------------
extern "C" void kernel_launch(void* const* d_in, const int* in_sizes, int n_in,
                              void* d_out, int out_size) {
    (void)in_sizes; (void)n_in; (void)out_size;
    const float* stim_spat = (const float*)d_in[0];
    const float* stim_time = (const float*)d_in[1];
    const float* init      = (const float*)d_in[2];
    const float* cc        = (const float*)d_in[3];
    const float* sf        = (const float*)d_in[4];
    const float* bias      = (const float*)d_in[5];
    const float* stf       = (const float*)d_in[6];
    const float* ff        = (const float*)d_in[7];
    const float* cK        = (const float*)d_in[8];
    const float* u         = (const float*)d_in[9];
    float* out = (float*)d_out;

    int pack_threads = B_ * NC_ * NW_ * 32;
    k_pack<<<(pack_threads + 255) / 256, 256>>>(cc);

    k_filt<<<(FT_ * 32 + 255) / 256, 256>>>(stim_time, stf);
    k_stimdot<<<(B_ * 32 + 255) / 256, 256>>>(stim_spat, sf);

    // transpose u -> uT[seq][t] (padded stride 1760)
    dim3 gtr((LS_ + 31) / 32, NSEQ_ / 32);
    k_utr<<<gtr, 256>>>(u);

    dim3 g3((LS_ + 255) / 256, B_);
    k_gensig<<<g3, 256>>>(cK, bias);

    // 4096 warps (4 sequences each) -> 1024 blocks of 128 threads
    k_sim<<<1024, 128>>>(init, ff, out);
}

// round 9
// speedup vs baseline: 1.2888x; 1.2888x over previous
#include <cuda_runtime.h>
#include <math.h>

#define B_   128
#define P_   2048
#define NB_  2000
#define NF_  250
#define NC_  16
#define R_   128
#define LS_  1750      // NB - NF
#define FT_  1751      // NB - NF + 1
#define NW_  63        // 32-bit words covering NB=2000
#define NWP_ 64        // padded row stride in words
#define LSP_ 1760      // padded LS stride (multiple of 32; covers transpose tile
                       // stores up to t=1759 and k_sim float4 reads in-row)
#define NSEQ_ (B_ * R_)

// ---------------- scratch (static device globals; no allocations) ----------------
__device__ float d_filt[FT_];
__device__ float d_stimdot[B_];
__device__ float d_gensig[B_ * LS_];
__device__ unsigned d_bm[B_ * NC_ * NWP_];      // bitmask of cc != 0
__device__ float d_uT[(size_t)NSEQ_ * LSP_];    // u transposed: [seq][t]

// ---------------- K1: filt_time ----------------
__global__ void k_filt(const float* __restrict__ stim_time,
                       const float* __restrict__ stf) {
    int warp = (blockIdx.x * blockDim.x + threadIdx.x) >> 5;
    int lane = threadIdx.x & 31;
    if (warp >= FT_) return;
    double a = 0.0;
    #pragma unroll
    for (int i = lane; i < NF_; i += 32)
        a += (double)stim_time[warp + i] * (double)stf[i];
    #pragma unroll
    for (int m = 16; m; m >>= 1) a += __shfl_xor_sync(0xffffffffu, a, m);
    if (lane == 0) d_filt[warp] = (float)a;
}

// ---------------- K2: stim_dot ----------------
__global__ void k_stimdot(const float* __restrict__ spat,
                          const float* __restrict__ sf) {
    int warp = (blockIdx.x * blockDim.x + threadIdx.x) >> 5;
    int lane = threadIdx.x & 31;
    if (warp >= B_) return;
    const float* row = spat + (size_t)warp * P_;
    double a = 0.0;
    for (int p = lane; p < P_; p += 32)
        a += (double)row[p] * (double)sf[p];
    #pragma unroll
    for (int m = 16; m; m >>= 1) a += __shfl_xor_sync(0xffffffffu, a, m);
    if (lane == 0) d_stimdot[warp] = (float)a;
}

// ---------------- K-pack: bitmask of cc != 0 ----------------
__global__ void k_pack(const float* __restrict__ cc) {
    int gid  = blockIdx.x * blockDim.x + threadIdx.x;
    int warp = gid >> 5;
    int lane = gid & 31;
    int row  = warp / NW_;
    int word = warp - row * NW_;
    if (row >= B_ * NC_) return;
    int elem = word * 32 + lane;
    float v = (elem < NB_) ? cc[(size_t)row * NB_ + elem] : 0.0f;
    unsigned m = __ballot_sync(0xffffffffu, v != 0.0f);
    if (lane == 0) d_bm[row * NWP_ + word] = m;
}

// ---------------- K-utr: transpose u[t][seq] -> uT[seq][t] (padded) ----------------
__global__ void __launch_bounds__(256)
k_utr(const float* __restrict__ u) {
    __shared__ float tile[32][33];
    const int tb = blockIdx.x;       // t-tile
    const int sb = blockIdx.y;       // seq-tile
    const int tx = threadIdx.x & 31;
    const int ty = threadIdx.x >> 5; // 0..7

    #pragma unroll
    for (int j = 0; j < 4; ++j) {
        int t = tb * 32 + ty + 8 * j;
        int s = sb * 32 + tx;
        tile[ty + 8 * j][tx] = (t < LS_) ? u[(size_t)t * NSEQ_ + s] : 0.0f;
    }
    __syncthreads();
    #pragma unroll
    for (int j = 0; j < 4; ++j) {
        int s = sb * 32 + ty + 8 * j;
        int t = tb * 32 + tx;        // <= 1759 < LSP_: in-row
        d_uT[(size_t)s * LSP_ + t] = tile[tx][ty + 8 * j];
    }
}

// ---------------- K3: gensig (verified R5 version, untouched) ----------------
__global__ void __launch_bounds__(256)
k_gensig(const float* __restrict__ cK,
         const float* __restrict__ bias) {
    __shared__ double sKd[NC_ * 256];
    __shared__ unsigned sbm[NC_ * NWP_];

    const int tid = threadIdx.x;
    const int b   = blockIdx.y;

    for (int i = tid; i < NC_ * 256; i += 256) {
        int c = i >> 8, k = i & 255;
        sKd[i] = (k < NF_) ? (double)cK[c * NF_ + k] : 0.0;
    }
    for (int i = tid; i < NC_ * NWP_; i += 256)
        sbm[i] = d_bm[b * NC_ * NWP_ + i];
    __syncthreads();

    const int t = blockIdx.x * 256 + tid;
    if (t >= LS_) return;

    const int w0 = t >> 5;
    const int o  = t & 31;

    double a0 = 0.0, a1 = 0.0, a2 = 0.0, a3 = 0.0;
    #pragma unroll 1
    for (int c = 0; c < NC_; ++c) {
        const unsigned* bm = sbm + c * NWP_ + w0;
        const double*   kd = sKd + c * 256;
        #pragma unroll
        for (int k = 0; k < 8; k += 4) {
            unsigned w_0 = __funnelshift_r(bm[k],     bm[k + 1], o);
            unsigned w_1 = __funnelshift_r(bm[k + 1], bm[k + 2], o);
            unsigned w_2 = __funnelshift_r(bm[k + 2], bm[k + 3], o);
            unsigned w_3 = __funnelshift_r(bm[k + 3], bm[k + 4], o);
            while (w_0) { int i = __ffs(w_0) - 1; w_0 &= w_0 - 1; a0 += kd[((k    ) << 5) + i]; }
            while (w_1) { int i = __ffs(w_1) - 1; w_1 &= w_1 - 1; a1 += kd[((k + 1) << 5) + i]; }
            while (w_2) { int i = __ffs(w_2) - 1; w_2 &= w_2 - 1; a2 += kd[((k + 2) << 5) + i]; }
            while (w_3) { int i = __ffs(w_3) - 1; w_3 &= w_3 - 1; a3 += kd[((k + 3) << 5) + i]; }
        }
    }
    float coup = (float)((a0 + a1) + (a2 + a3));
    float sg = __fmul_rn(d_stimdot[b], d_filt[t]);
    sg = __fadd_rn(sg, bias[0]);
    d_gensig[b * LS_ + t] = __fadd_rn(sg, coup);
}

// ---------------- K4: simulation — R3 geometry + coalesced u, NO reg cap --------
// 4 sequences/warp, 8 lanes/seq, 32 taps/lane, rotation mod 32, 32-step blocks.
// __launch_bounds__(128) only: compiler keeps ~90 regs (no spills; R8's ",6"
// cap spilled into the inner loop and cost ~300us).
__global__ void __launch_bounds__(128)
k_sim(const float* __restrict__ init,
      const float* __restrict__ ff,
      float* __restrict__ out) {
    const unsigned FULL = 0xffffffffu;
    const int lane = threadIdx.x & 31;
    const int gw   = (blockIdx.x * blockDim.x + threadIdx.x) >> 5;  // 0..4095
    const int b    = gw >> 5;         // 32 warps per b
    const int rq   = gw & 31;
    const int half = lane >> 3;       // 0..3: sequence within the warp
    const int q    = lane & 7;        // lane within the 8-lane group
    const int seq  = b * R_ + rq * 4 + half;

    float f[32], w[32];
    #pragma unroll
    for (int i = 0; i < 32; ++i) {
        int k = q * 32 + i;
        bool valid = (k < NF_);
        f[i] = valid ? ff[k] : 0.0f;
        w[i] = valid ? init[b * NF_ + k] : 0.0f;
    }

    float* orow = out + (size_t)seq * NB_;
    for (int k = q; k < NF_; k += 8)
        orow[k] = init[b * NF_ + k];

    const float* gens = d_gensig + b * LS_;
    const float* urow = d_uT + (size_t)seq * LSP_;
    const int src_half  = lane & 24;
    const int src_shift = src_half | ((q + 1) & 7);

    for (int t0 = 0; t0 < LS_; t0 += 32) {
        float gval = (t0 + lane < LS_) ? gens[t0 + lane] : 0.0f;
        // lane q holds u for t = t0+4q .. t0+4q+3 (128B contiguous per group)
        float4 uv = *(const float4*)(urow + t0 + 4 * q);
        float outv[4];
        outv[0] = outv[1] = outv[2] = outv[3] = 0.0f;

        #pragma unroll
        for (int s = 0; s < 32; ++s) {
            float a  = w[s & 31]        * f[0];
            float bb = w[(16 + s) & 31] * f[16];
            #pragma unroll
            for (int i = 1; i < 16; ++i) {
                a  = fmaf(w[(i + s) & 31],      f[i],      a);
                bb = fmaf(w[(16 + i + s) & 31], f[16 + i], bb);
            }
            float acc = a + bb;
            acc += __shfl_xor_sync(FULL, acc, 1);
            acc += __shfl_xor_sync(FULL, acc, 2);
            acc += __shfl_xor_sync(FULL, acc, 4);

            float gt = __shfl_sync(FULL, gval, s);
            float uu = (s & 3) == 0 ? uv.x : (s & 3) == 1 ? uv.y
                     : (s & 3) == 2 ? uv.z : uv.w;
            float ut = __shfl_sync(FULL, uu, src_half | (s >> 2));

            float g = gt + acc;
            float e = expf(-g);
            float sig = 1.0f / (1.0f + e);
            float spike = (ut < sig) ? 1.0f : 0.0f;

            if (q == (s & 7)) outv[s >> 3] = spike;

            float inc = __shfl_sync(FULL, w[s & 31], src_shift);
            w[s & 31] = inc;
            if (q == 7) w[(s + 26) & 31] = spike;
        }

        #pragma unroll
        for (int m = 0; m < 4; ++m) {
            int t = t0 + 8 * m + q;
            if (t < LS_) orow[NF_ + t] = outv[m];
        }
    }
}

// ---------------- launch ----------------
extern "C" void kernel_launch(void* const* d_in, const int* in_sizes, int n_in,
                              void* d_out, int out_size) {
    (void)in_sizes; (void)n_in; (void)out_size;
    const float* stim_spat = (const float*)d_in[0];
    const float* stim_time = (const float*)d_in[1];
    const float* init      = (const float*)d_in[2];
    const float* cc        = (const float*)d_in[3];
    const float* sf        = (const float*)d_in[4];
    const float* bias      = (const float*)d_in[5];
    const float* stf       = (const float*)d_in[6];
    const float* ff        = (const float*)d_in[7];
    const float* cK        = (const float*)d_in[8];
    const float* u         = (const float*)d_in[9];
    float* out = (float*)d_out;

    int pack_threads = B_ * NC_ * NW_ * 32;
    k_pack<<<(pack_threads + 255) / 256, 256>>>(cc);

    k_filt<<<(FT_ * 32 + 255) / 256, 256>>>(stim_time, stf);
    k_stimdot<<<(B_ * 32 + 255) / 256, 256>>>(stim_spat, sf);

    // transpose u -> uT[seq][t] (padded stride 1760)
    dim3 gtr((LS_ + 31) / 32, NSEQ_ / 32);
    k_utr<<<gtr, 256>>>(u);

    dim3 g3((LS_ + 255) / 256, B_);
    k_gensig<<<g3, 256>>>(cK, bias);

    // 4096 warps (4 sequences each) -> 1024 blocks of 128 threads
    k_sim<<<1024, 128>>>(init, ff, out);
}

// round 10
// speedup vs baseline: 1.4149x; 1.0978x over previous
#include <cuda_runtime.h>
#include <math.h>

#define B_   128
#define P_   2048
#define NB_  2000
#define NF_  250
#define NC_  16
#define R_   128
#define LS_  1750      // NB - NF
#define FT_  1751      // NB - NF + 1
#define NW_  63        // 32-bit words covering NB=2000
#define NWP_ 64        // padded row stride in words

// ---------------- scratch (static device globals; no allocations) ----------------
__device__ float d_filt[FT_];
__device__ float d_stimdot[B_];
__device__ float d_gensig[B_ * LS_];
__device__ unsigned d_bm[B_ * NC_ * NWP_];   // bitmask of cc != 0

// ---------------- K1: filt_time ----------------
__global__ void k_filt(const float* __restrict__ stim_time,
                       const float* __restrict__ stf) {
    int warp = (blockIdx.x * blockDim.x + threadIdx.x) >> 5;
    int lane = threadIdx.x & 31;
    if (warp >= FT_) return;
    double a = 0.0;
    #pragma unroll
    for (int i = lane; i < NF_; i += 32)
        a += (double)stim_time[warp + i] * (double)stf[i];
    #pragma unroll
    for (int m = 16; m; m >>= 1) a += __shfl_xor_sync(0xffffffffu, a, m);
    if (lane == 0) d_filt[warp] = (float)a;
}

// ---------------- K2: stim_dot ----------------
__global__ void k_stimdot(const float* __restrict__ spat,
                          const float* __restrict__ sf) {
    int warp = (blockIdx.x * blockDim.x + threadIdx.x) >> 5;
    int lane = threadIdx.x & 31;
    if (warp >= B_) return;
    const float* row = spat + (size_t)warp * P_;
    double a = 0.0;
    for (int p = lane; p < P_; p += 32)
        a += (double)row[p] * (double)sf[p];
    #pragma unroll
    for (int m = 16; m; m >>= 1) a += __shfl_xor_sync(0xffffffffu, a, m);
    if (lane == 0) d_stimdot[warp] = (float)a;
}

// ---------------- K-pack: bitmask of cc != 0 ----------------
__global__ void k_pack(const float* __restrict__ cc) {
    int gid  = blockIdx.x * blockDim.x + threadIdx.x;
    int warp = gid >> 5;
    int lane = gid & 31;
    int row  = warp / NW_;
    int word = warp - row * NW_;
    if (row >= B_ * NC_) return;
    int elem = word * 32 + lane;
    float v = (elem < NB_) ? cc[(size_t)row * NB_ + elem] : 0.0f;
    unsigned m = __ballot_sync(0xffffffffu, v != 0.0f);
    if (lane == 0) d_bm[row * NWP_ + word] = m;
}

// ---------------- K3: gensig — 8 rotating double accumulators ----------------
// One accumulator per bitmask word: serial DADD chain depth ~25 instead of ~50.
// Double-sum reassociation only; float conversion unchanged in distribution.
__global__ void __launch_bounds__(256)
k_gensig(const float* __restrict__ cK,
         const float* __restrict__ bias) {
    __shared__ double sKd[NC_ * 256];          // taps zero-padded 250 -> 256
    __shared__ unsigned sbm[NC_ * NWP_];

    const int tid = threadIdx.x;
    const int b   = blockIdx.y;

    for (int i = tid; i < NC_ * 256; i += 256) {
        int c = i >> 8, k = i & 255;
        sKd[i] = (k < NF_) ? (double)cK[c * NF_ + k] : 0.0;
    }
    for (int i = tid; i < NC_ * NWP_; i += 256)
        sbm[i] = d_bm[b * NC_ * NWP_ + i];
    __syncthreads();

    const int t = blockIdx.x * 256 + tid;
    if (t >= LS_) return;

    const int w0 = t >> 5;
    const int o  = t & 31;

    double a0 = 0.0, a1 = 0.0, a2 = 0.0, a3 = 0.0;
    double a4 = 0.0, a5 = 0.0, a6 = 0.0, a7 = 0.0;
    #pragma unroll 1
    for (int c = 0; c < NC_; ++c) {
        const unsigned* bm = sbm + c * NWP_ + w0;
        const double*   kd = sKd + c * 256;
        unsigned m0 = __funnelshift_r(bm[0], bm[1], o);
        unsigned m1 = __funnelshift_r(bm[1], bm[2], o);
        unsigned m2 = __funnelshift_r(bm[2], bm[3], o);
        unsigned m3 = __funnelshift_r(bm[3], bm[4], o);
        unsigned m4 = __funnelshift_r(bm[4], bm[5], o);
        unsigned m5 = __funnelshift_r(bm[5], bm[6], o);
        unsigned m6 = __funnelshift_r(bm[6], bm[7], o);
        unsigned m7 = __funnelshift_r(bm[7], bm[8], o);
        while (m0) { int i = __ffs(m0) - 1; m0 &= m0 - 1; a0 += kd[  0 + i]; }
        while (m1) { int i = __ffs(m1) - 1; m1 &= m1 - 1; a1 += kd[ 32 + i]; }
        while (m2) { int i = __ffs(m2) - 1; m2 &= m2 - 1; a2 += kd[ 64 + i]; }
        while (m3) { int i = __ffs(m3) - 1; m3 &= m3 - 1; a3 += kd[ 96 + i]; }
        while (m4) { int i = __ffs(m4) - 1; m4 &= m4 - 1; a4 += kd[128 + i]; }
        while (m5) { int i = __ffs(m5) - 1; m5 &= m5 - 1; a5 += kd[160 + i]; }
        while (m6) { int i = __ffs(m6) - 1; m6 &= m6 - 1; a6 += kd[192 + i]; }
        while (m7) { int i = __ffs(m7) - 1; m7 &= m7 - 1; a7 += kd[224 + i]; }
    }
    float coup = (float)(((a0 + a1) + (a2 + a3)) + ((a4 + a5) + (a6 + a7)));
    float sg = __fmul_rn(d_stimdot[b], d_filt[t]);
    sg = __fadd_rn(sg, bias[0]);
    d_gensig[b * LS_ + t] = __fadd_rn(sg, coup);
}

// ---------------- K4: simulation — R3 version verbatim (verified, ~700us) ------
// 4 sequences/warp, 8 lanes/seq, 32 taps/lane, rotation mod 32, 32-step blocks,
// direct (uncoalesced) u loads — measured faster than all alternatives tried.
__global__ void __launch_bounds__(128)
k_sim(const float* __restrict__ init,
      const float* __restrict__ ff,
      const float* __restrict__ u,
      float* __restrict__ out) {
    const unsigned FULL = 0xffffffffu;
    const int lane = threadIdx.x & 31;
    const int gw   = (blockIdx.x * blockDim.x + threadIdx.x) >> 5;  // 0..4095
    const int b    = gw >> 5;         // 32 warps per b
    const int rq   = gw & 31;
    const int half = lane >> 3;       // 0..3: sequence within the warp
    const int q    = lane & 7;        // lane within the 8-lane group
    const int seq  = b * R_ + rq * 4 + half;

    float f[32], w[32];
    #pragma unroll
    for (int i = 0; i < 32; ++i) {
        int k = q * 32 + i;
        bool valid = (k < NF_);
        f[i] = valid ? ff[k] : 0.0f;
        w[i] = valid ? init[b * NF_ + k] : 0.0f;
    }

    float* orow = out + (size_t)seq * NB_;
    for (int k = q; k < NF_; k += 8)
        orow[k] = init[b * NF_ + k];

    const float* gens = d_gensig + b * LS_;
    const int src_half  = lane & 24;
    const int src_shift = src_half | ((q + 1) & 7);

    for (int t0 = 0; t0 < LS_; t0 += 32) {
        float gval = (t0 + lane < LS_) ? gens[t0 + lane] : 0.0f;
        float uval[4], outv[4];
        #pragma unroll
        for (int m = 0; m < 4; ++m) {
            int t = t0 + 8 * m + q;
            uval[m] = (t < LS_) ? u[(size_t)t * (B_ * R_) + seq] : 0.0f;
            outv[m] = 0.0f;
        }

        #pragma unroll
        for (int s = 0; s < 32; ++s) {
            float a  = w[s & 31]        * f[0];
            float bb = w[(16 + s) & 31] * f[16];
            #pragma unroll
            for (int i = 1; i < 16; ++i) {
                a  = fmaf(w[(i + s) & 31],      f[i],      a);
                bb = fmaf(w[(16 + i + s) & 31], f[16 + i], bb);
            }
            float acc = a + bb;
            acc += __shfl_xor_sync(FULL, acc, 1);
            acc += __shfl_xor_sync(FULL, acc, 2);
            acc += __shfl_xor_sync(FULL, acc, 4);

            float gt = __shfl_sync(FULL, gval, s);
            float ut = __shfl_sync(FULL, uval[s >> 3], src_half | (s & 7));

            float g = gt + acc;
            float e = expf(-g);
            float sig = 1.0f / (1.0f + e);
            float spike = (ut < sig) ? 1.0f : 0.0f;

            if (q == (s & 7)) outv[s >> 3] = spike;

            float inc = __shfl_sync(FULL, w[s & 31], src_shift);
            w[s & 31] = inc;
            if (q == 7) w[(s + 26) & 31] = spike;
        }

        #pragma unroll
        for (int m = 0; m < 4; ++m) {
            int t = t0 + 8 * m + q;
            if (t < LS_) orow[NF_ + t] = outv[m];
        }
    }
}

// ---------------- launch ----------------
extern "C" void kernel_launch(void* const* d_in, const int* in_sizes, int n_in,
                              void* d_out, int out_size) {
    (void)in_sizes; (void)n_in; (void)out_size;
    const float* stim_spat = (const float*)d_in[0];
    const float* stim_time = (const float*)d_in[1];
    const float* init      = (const float*)d_in[2];
    const float* cc        = (const float*)d_in[3];
    const float* sf        = (const float*)d_in[4];
    const float* bias      = (const float*)d_in[5];
    const float* stf       = (const float*)d_in[6];
    const float* ff        = (const float*)d_in[7];
    const float* cK        = (const float*)d_in[8];
    const float* u         = (const float*)d_in[9];
    float* out = (float*)d_out;

    int pack_threads = B_ * NC_ * NW_ * 32;
    k_pack<<<(pack_threads + 255) / 256, 256>>>(cc);

    k_filt<<<(FT_ * 32 + 255) / 256, 256>>>(stim_time, stf);
    k_stimdot<<<(B_ * 32 + 255) / 256, 256>>>(stim_spat, sf);

    dim3 g3((LS_ + 255) / 256, B_);
    k_gensig<<<g3, 256>>>(cK, bias);

    // 4096 warps (4 sequences each) -> 1024 blocks of 128 threads
    k_sim<<<1024, 128>>>(init, ff, u, out);
}